// round 13
// baseline (speedup 1.0000x reference)
#include <cuda_runtime.h>
#include <cuda_bf16.h>
#include <math.h>
#include <float.h>

// HierarchyLoss: out = mean_b( lse(logits[b]) - logits[b,label[b]] )
//              + 0.1 * sum_e ||emb[parent[e]] - emb[child[e]]||^2
//
// Inputs (index tensors are int32):
//  0: logits float32 [B,N]  1: labels int32 [B]  2: label_emb float32 [N,D]
//  3: parent_idx int32 [E]  4: child_idx int32 [E]      Output: f32 scalar.
//
// Persistent single-wave kernel: 1776 blocks = 12/SM x 148 SM (128 thr, <=42
// regs via launch_bounds). Warp 0 of blocks [0,1024) -> LSE task; warp 0 of
// blocks [1024,1776) joins the edge pool; warps 1-3 always edges.
// Last-arriving block (self-resetting ticket) does the deterministic combine.

#define G_BLOCKS   1776            // 12 blocks/SM * 148 SMs — ONE wave
#define THREADS    128
#define NWARPS     4
#define EDGE_WPB   3               // warps 1..3
#define LSE_SPLIT  8               // B * 8 = 1024 LSE tasks (warp 0, blk<1024)
#define MAX_B      256
#define HIER_W     0.1f

// Scratch (allocation-free rule: __device__ globals)
__device__ float        g_lse_m[MAX_B * LSE_SPLIT];
__device__ float        g_lse_s[MAX_B * LSE_SPLIT];
__device__ float        g_edge_part[G_BLOCKS];
__device__ float        g_ce_logit[MAX_B];
__device__ unsigned int g_count = 0;          // auto-wrap ticket (replay-safe)

__global__ void __launch_bounds__(THREADS, 12)
hierarchy_loss_kernel(const float* __restrict__ logits,
                      const int*   __restrict__ labels,
                      const float* __restrict__ emb,
                      const int*   __restrict__ par,
                      const int*   __restrict__ chi,
                      float* __restrict__ out,
                      int B, int N, int E, int D)
{
    const int t    = threadIdx.x;
    const int warp = t >> 5;
    const int lane = t & 31;
    const int blk  = blockIdx.x;

    const int tasks = min(B * LSE_SPLIT, G_BLOCKS);          // 1024
    // edge-warp id space: warps 1-3 of every block, plus warp 0 of blocks
    // that have no LSE task. Total pool size:
    const int n_edge_warps = G_BLOCKS * EDGE_WPB + (G_BLOCKS - tasks); // 6080

    // ---- label-logit prefetch (block 0): warm g_ce_logit early -----------
    if (blk == 0 && t < B) {
        int lab = min(max(labels[t], 0), N - 1);
        g_ce_logit[t] = logits[(size_t)t * N + lab];
    }

    float edge_acc = 0.0f;
    bool  do_lse   = (warp == 0) && (blk < tasks);

    if (do_lse) {
        // ================= LSE: one warp per (row, part) task =============
        const int task = blk;
        const int row  = task / LSE_SPLIT;
        const int part = task % LSE_SPLIT;
        const int vecN = N >> 2;                  // N % 4 == 0
        const int chunk = (vecN + LSE_SPLIT - 1) / LSE_SPLIT;
        const int c0 = part * chunk;
        const int c1 = min(c0 + chunk, vecN);

        const float4* __restrict__ p =
            reinterpret_cast<const float4*>(logits + (size_t)row * N);

        float m = -FLT_MAX, s = 0.0f;
        for (int i = c0 + lane; i < c1; i += 32) {
            float4 v = __ldcs(p + i);             // streaming: read-once
            float mv = fmaxf(fmaxf(v.x, v.y), fmaxf(v.z, v.w));
            if (mv > m) { s *= __expf(m - mv); m = mv; }
            s += __expf(v.x - m) + __expf(v.y - m) +
                 __expf(v.z - m) + __expf(v.w - m);
        }
        #pragma unroll
        for (int off = 16; off > 0; off >>= 1) {  // deterministic butterfly
            float m2 = __shfl_xor_sync(0xffffffffu, m, off);
            float s2 = __shfl_xor_sync(0xffffffffu, s, off);
            float M  = fmaxf(m, m2);
            s = s * __expf(m - M) + s2 * __expf(m2 - M);
            m = M;
        }
        if (lane == 0) { g_lse_m[task] = m; g_lse_s[task] = s; }
    } else {
        // ================= Edge pool: warp-strided edges ==================
        int ew;
        if (warp == 0) ew = G_BLOCKS * EDGE_WPB + (blk - tasks);
        else           ew = blk * EDGE_WPB + (warp - 1);

        int e  = ew;
        int pi = (e < E) ? __ldcs(par + e) : 0;
        int ci = (e < E) ? __ldcs(chi + e) : 0;

        if (D == 256) {
            // 64 float4/row; lane covers [lane] and [lane+32]
            while (e < E) {
                const int en = e + n_edge_warps;
                int pn = (en < E) ? __ldcs(par + en) : 0;   // prefetch next
                int cn = (en < E) ? __ldcs(chi + en) : 0;

                pi = min(max(pi, 0), N - 1);
                ci = min(max(ci, 0), N - 1);

                const float4* __restrict__ pp =
                    reinterpret_cast<const float4*>(emb + (size_t)pi * 256);
                const float4* __restrict__ pc =
                    reinterpret_cast<const float4*>(emb + (size_t)ci * 256);

                float4 a0 = pp[lane];
                float4 a1 = pp[lane + 32];
                float4 b0 = pc[lane];
                float4 b1 = pc[lane + 32];

                float dx = a0.x - b0.x, dy = a0.y - b0.y;
                float dz = a0.z - b0.z, dw = a0.w - b0.w;
                edge_acc += dx*dx + dy*dy + dz*dz + dw*dw;
                dx = a1.x - b1.x; dy = a1.y - b1.y;
                dz = a1.z - b1.z; dw = a1.w - b1.w;
                edge_acc += dx*dx + dy*dy + dz*dz + dw*dw;

                e = en; pi = pn; ci = cn;
            }
        } else {
            const int vecD = D >> 2;
            while (e < E) {
                const int en = e + n_edge_warps;
                int pn = (en < E) ? __ldcs(par + en) : 0;
                int cn = (en < E) ? __ldcs(chi + en) : 0;
                pi = min(max(pi, 0), N - 1);
                ci = min(max(ci, 0), N - 1);
                const float4* __restrict__ pp =
                    reinterpret_cast<const float4*>(emb + (size_t)pi * D);
                const float4* __restrict__ pc =
                    reinterpret_cast<const float4*>(emb + (size_t)ci * D);
                for (int i = lane; i < vecD; i += 32) {
                    float4 a = pp[i], b = pc[i];
                    float dx = a.x - b.x, dy = a.y - b.y;
                    float dz = a.z - b.z, dw = a.w - b.w;
                    edge_acc += dx*dx + dy*dy + dz*dz + dw*dw;
                }
                e = en; pi = pn; ci = cn;
            }
        }
    }

    // ---- per-block edge reduction (LSE warp contributes 0) ---------------
    #pragma unroll
    for (int off = 16; off > 0; off >>= 1)
        edge_acc += __shfl_xor_sync(0xffffffffu, edge_acc, off);

    __shared__ float s_warp[NWARPS];
    if (lane == 0) s_warp[warp] = edge_acc;
    __syncthreads();
    if (t == 0) {
        float bsum = 0.0f;
        #pragma unroll
        for (int w = 0; w < NWARPS; w++) bsum += s_warp[w];
        g_edge_part[blk] = bsum;
    }

    // ---- completion ticket ----------------------------------------------
    __shared__ bool s_last;
    if (t == 0) {
        __threadfence();
        unsigned int ticket = atomicInc(&g_count, G_BLOCKS - 1); // wraps->0
        s_last = (ticket == G_BLOCKS - 1);
    }
    __syncthreads();
    if (!s_last) return;

    // ================= final combine (last block, deterministic) =========
    __threadfence();

    float v = 0.0f;
    if (t < B) {
        float m = g_lse_m[t * LSE_SPLIT];
        float s = g_lse_s[t * LSE_SPLIT];
        #pragma unroll
        for (int p = 1; p < LSE_SPLIT; p++) {
            float m2 = g_lse_m[t * LSE_SPLIT + p];
            float s2 = g_lse_s[t * LSE_SPLIT + p];
            float M  = fmaxf(m, m2);
            s = s * __expf(m - M) + s2 * __expf(m2 - M);
            m = M;
        }
        v = (m + logf(s) - g_ce_logit[t]) / (float)B;
    }

    float ep = 0.0f;
    for (int i = t; i < G_BLOCKS; i += THREADS) ep += g_edge_part[i];
    v += HIER_W * ep;

    __shared__ float red[THREADS];
    red[t] = v;
    __syncthreads();
    #pragma unroll
    for (int off = THREADS / 2; off > 0; off >>= 1) {
        if (t < off) red[t] += red[t + off];
        __syncthreads();
    }
    if (t == 0) out[0] = red[0];
}

// ---------------------------------------------------------------------------
extern "C" void kernel_launch(void* const* d_in, const int* in_sizes, int n_in,
                              void* d_out, int out_size)
{
    const float* logits = (const float*)d_in[0];
    const int*   labels = (const int*)d_in[1];
    const float* emb    = (const float*)d_in[2];
    const int*   par    = (const int*)d_in[3];
    const int*   chi    = (const int*)d_in[4];
    float*       out    = (float*)d_out;

    const int B = in_sizes[1];                // 128
    const int N = in_sizes[0] / B;            // 100000
    const int D = in_sizes[2] / N;            // 256
    const int E = in_sizes[3];                // 99999

    hierarchy_loss_kernel<<<G_BLOCKS, THREADS>>>(logits, labels, emb, par, chi,
                                                 out, B, N, E, D);
}